// round 11
// baseline (speedup 1.0000x reference)
#include <cuda_runtime.h>
#include <cuda_fp16.h>
#include <cstdint>

// Problem dims (fixed)
#define Bv 64
#define Hv 128
#define Wv 128
#define Cv 3
#define Nv 10

#define ROWS 32                // output rows per CTA
#define SRR2 37                // staged strip rows (32 + 4 halo + 1 overrun row)
#define WPR 36                 // fp16x2 words per row (72 pixels)
#define SST2 40                // word stride per row
#define CPYB_OFF (SRR2 * SST2 + 16)   // odd-pair copy base (+16 words = bank shift)
#define PXB 64                 // pixels (width) per CTA
#define NT 128                 // 4 warps, one 16-px col tile each

__device__ __forceinline__ void mma_f16(float c[4], uint32_t a0, uint32_t a1,
                                        uint32_t a2, uint32_t a3,
                                        uint32_t b0, uint32_t b1) {
    asm("mma.sync.aligned.m16n8k16.row.col.f32.f16.f16.f32 "
        "{%0,%1,%2,%3}, {%4,%5,%6,%7}, {%8,%9}, {%0,%1,%2,%3};"
        : "+f"(c[0]), "+f"(c[1]), "+f"(c[2]), "+f"(c[3])
        : "r"(a0), "r"(a1), "r"(a2), "r"(a3), "r"(b0), "r"(b1));
}

// out[n][b][c][h][w] = sum_{kh,kw} images[b][h+kh-2][w+kw-2][c] * kernels[b][kh][kw][n]
// fp16 m16n8k16 implicit GEMM. K groups of 16 = 2 kh rows x 8 kw slots (kw 5..7
// zero-weighted). Fragment F(ai) = strip rows (ai, ai+1) serves G0/G1/G2 of
// output rows ai, ai-2, ai-4; row-to-row carry leaves 2 LDS per strip row.
__global__ __launch_bounds__(NT, 6)
void cdna_mma_kernel(const float* __restrict__ images,
                     const float* __restrict__ kernels,
                     float* __restrict__ out)
{
    __shared__ uint32_t strip[CPYB_OFF + SRR2 * SST2];  // fp16x2 even/odd pair copies
    __shared__ uint32_t pairW[6 * 4 * 16];              // [kh][tg][n] fp16x2 kw-pairs

    const int tid  = threadIdx.x;
    const int lane = tid & 31;
    const int wrp  = tid >> 5;         // 0..3: 16-px column tile
    const int g    = lane >> 2;        // 0..7
    const int tg   = lane & 3;         // 0..3

    const int bx = blockIdx.x & 1;     // width half
    const int rt = blockIdx.x >> 1;    // row tile 0..3
    const int c  = blockIdx.y;
    const int b  = blockIdx.z;
    const int r0 = rt * ROWS;
    const int px0 = bx * PXB;

    // ---- stage W pairs: pairW[kh][tg][n] = fp16x2 (W[kh][2tg][n], W[kh][2tg+1][n]) ----
    for (int i = tid; i < 384; i += NT) {
        int kh = i >> 6, rem = i & 63, t = rem >> 4, n = rem & 15;
        int kw0 = 2 * t, kw1 = 2 * t + 1;
        float v0 = 0.0f, v1 = 0.0f;
        if (kh < 5 && n < Nv) {
            if (kw0 < 5) v0 = kernels[(b * 25 + kh * 5 + kw0) * Nv + n];
            if (kw1 < 5) v1 = kernels[(b * 25 + kh * 5 + kw1) * Nv + n];
        }
        __half2 h = __floats2half2_rn(v0, v1);
        pairW[i] = *reinterpret_cast<uint32_t*>(&h);
    }

    // ---- stage fp16 strip, even-pair copy A (px 2j,2j+1) + odd copy B (2j+1,2j+2) ----
    const float* imgb = images + ((size_t)b * Hv) * (Wv * Cv) + c;
    for (int i = tid; i < SRR2 * WPR; i += NT) {
        int r = i / WPR, j = i - r * WPR;
        int gh = r0 + r - 2;
        int gw0 = px0 + 2 * j - 2;
        float f0 = 0.0f, f1 = 0.0f, f2 = 0.0f;
        if (gh >= 0 && gh < Hv) {
            const float* row = imgb + (size_t)gh * Wv * Cv;
            if (gw0     >= 0 && gw0     < Wv) f0 = row[gw0 * Cv];
            if (gw0 + 1 >= 0 && gw0 + 1 < Wv) f1 = row[(gw0 + 1) * Cv];
            if (gw0 + 2 >= 0 && gw0 + 2 < Wv) f2 = row[(gw0 + 2) * Cv];
        }
        __half2 hA = __floats2half2_rn(f0, f1);
        __half2 hB = __floats2half2_rn(f1, f2);
        strip[r * SST2 + j]            = *reinterpret_cast<uint32_t*>(&hA);
        strip[CPYB_OFF + r * SST2 + j] = *reinterpret_cast<uint32_t*>(&hB);
    }
    __syncthreads();

    // ---- B fragments: bf[G][u][j] (j: kh=2G / 2G+1). G2's second half is zero. ----
    uint32_t bf[3][2][2];
    #pragma unroll
    for (int G = 0; G < 3; G++)
        #pragma unroll
        for (int u = 0; u < 2; u++) {
            bf[G][u][0] = pairW[(2 * G)     * 64 + tg * 16 + 8 * u + g];
            bf[G][u][1] = pairW[(2 * G + 1) * 64 + tg * 16 + 8 * u + g];
        }

    // ---- fragment base: pixel pair start p0 = x + 2tg; parity selects copy ----
    const int p0 = wrp * 16 + g + 2 * tg;
    const uint32_t* fbase = strip + ((p0 & 1) ? (CPYB_OFF + (p0 >> 1)) : (p0 >> 1));

    const size_t ns = (size_t)Bv * Cv * Hv * Wv;
    float* outbc = out + (((size_t)b * Cv + c) * Hv + r0) * Wv + px0;

    float acc[5][2][4] = {};

    uint32_t cur0 = fbase[0];          // strip row 0: px pair, px+8 pair
    uint32_t cur1 = fbase[4];
    fbase += SST2;

    #pragma unroll
    for (int ai = 0; ai < SRR2 - 1; ai++) {      // 36 iterations
        const uint32_t nxt0 = fbase[0];           // strip row ai+1
        const uint32_t nxt1 = fbase[4];
        fbase += SST2;

        #pragma unroll
        for (int G = 0; G < 3; G++) {
            const int r = ai - 2 * G;
            if (r >= 0 && r < ROWS) {
                const int sl = r % 5;
                mma_f16(acc[sl][0], cur0, cur1, nxt0, nxt1, bf[G][0][0], bf[G][0][1]);
                mma_f16(acc[sl][1], cur0, cur1, nxt0, nxt1, bf[G][1][0], bf[G][1][1]);
            }
        }

        const int rd = ai - 4;          // completed output row
        if (rd >= 0) {
            const int sl = rd % 5;
            float* orow = outbc + (size_t)rd * Wv + wrp * 16 + g;
            orow[(size_t)(2 * tg)     * ns]     = acc[sl][0][0];
            orow[(size_t)(2 * tg + 1) * ns]     = acc[sl][0][1];
            orow[(size_t)(2 * tg)     * ns + 8] = acc[sl][0][2];
            orow[(size_t)(2 * tg + 1) * ns + 8] = acc[sl][0][3];
            if (tg == 0) {               // n = 8, 9 (u=1 half)
                orow[8 * ns]     = acc[sl][1][0];
                orow[9 * ns]     = acc[sl][1][1];
                orow[8 * ns + 8] = acc[sl][1][2];
                orow[9 * ns + 8] = acc[sl][1][3];
            }
            #pragma unroll
            for (int u = 0; u < 2; u++)
                #pragma unroll
                for (int q = 0; q < 4; q++)
                    acc[sl][u][q] = 0.0f;
        }

        cur0 = nxt0;
        cur1 = nxt1;
    }
}

extern "C" void kernel_launch(void* const* d_in, const int* in_sizes, int n_in,
                              void* d_out, int out_size)
{
    const float* images  = (const float*)d_in[0];   // [B,H,W,C]
    const float* kernels = (const float*)d_in[1];   // [B,KH,KW,N]
    float* out = (float*)d_out;                     // [N,B,C,H,W]

    dim3 block(NT, 1, 1);
    dim3 grid((Wv / PXB) * (Hv / ROWS), Cv, Bv);   // (8, 3, 64)
    cdna_mma_kernel<<<grid, block>>>(images, kernels, out);
}

// round 12
// speedup vs baseline: 1.0072x; 1.0072x over previous
#include <cuda_runtime.h>
#include <cstdint>

// Problem dims (fixed)
#define Bv 64
#define Hv 128
#define Wv 128
#define Cv 3
#define Nv 10

#define ROWS 32                // output rows per CTA
#define SRR (ROWS + 4)         // 36 strip rows
#define PXB 64                 // pixels (width) per CTA
#define SCV (PXB + 4)          // 68 valid strip cols
#define SST 76                 // padded strip stride (76 % 32 = 12, conflict-free)
#define NT 128                 // 4 warps, one 16-px col tile each
#define NS (Bv * Cv * Hv * Wv) // output n-plane stride in elements (3.1M)

__device__ __forceinline__ uint32_t to_tf32(float v) {
    uint32_t u;
    asm("cvt.rna.tf32.f32 %0, %1;" : "=r"(u) : "f"(v));
    return u;
}

__device__ __forceinline__ void mma_tf32(float c[4], const uint32_t a[4],
                                         uint32_t b0, uint32_t b1) {
    asm("mma.sync.aligned.m16n8k8.row.col.f32.tf32.tf32.f32 "
        "{%0,%1,%2,%3}, {%4,%5,%6,%7}, {%8,%9}, {%0,%1,%2,%3};"
        : "+f"(c[0]), "+f"(c[1]), "+f"(c[2]), "+f"(c[3])
        : "r"(a[0]), "r"(a[1]), "r"(a[2]), "r"(a[3]), "r"(b0), "r"(b1));
}

// out[n][b][c][h][w] = sum_{kh,kw} images[b][h+kh-2][w+kw-2][c] * kernels[b][kh][kw][n]
// K laid out kh-major: k = 8*kh + kw (kw slots 5..7 zero). One strip-row fragment
// serves all 5 kh-groups (output rows ai .. ai-4) -> 4 LDS feed 10 MMAs.
__global__ __launch_bounds__(NT, 6)
void cdna_mma_kernel(const float* __restrict__ images,
                     const float* __restrict__ kernels,
                     float* __restrict__ out)
{
    __shared__ float strip[SRR * SST];   // tf32-rounded image strip
    __shared__ float Wsm[40][16];        // tf32-rounded weights [k=8kh+kw][n]

    const int tid  = threadIdx.x;
    const int lane = tid & 31;
    const int wrp  = tid >> 5;         // 0..3: 16-px column tile
    const int g    = lane >> 2;        // 0..7
    const int tg   = lane & 3;         // 0..3
    const bool t24 = (tg == 0);

    const int bx = blockIdx.x & 1;     // width half
    const int rt = blockIdx.x >> 1;    // row tile 0..3
    const int c  = blockIdx.y;
    const int b  = blockIdx.z;
    const int r0 = rt * ROWS;
    const int px0 = bx * PXB;

    // ---- stage W: [k=40][n=16], kh-major slots, tf32-rounded, pad -> 0 ----
    for (int i = tid; i < 640; i += NT) {
        int k = i >> 4, n = i & 15;
        int s = k >> 3, t = k & 7;
        float v = 0.0f;
        if (t < 5 && n < Nv) v = kernels[(b * 25 + s * 5 + t) * Nv + n];
        Wsm[k][n] = __uint_as_float(to_tf32(v));
    }

    // ---- stage image strip (tf32-rounded, zero-padded halo) ----
    const float* imgb = images + ((size_t)b * Hv) * (Wv * Cv) + c;
    #pragma unroll
    for (int it = 0; it < (SRR * SCV + NT - 1) / NT; it++) {
        int i = it * NT + tid;
        if (i < SRR * SCV) {
            int r  = i / SCV;
            int cc = i - r * SCV;
            int gh = r0 + r - 2;
            int gw = px0 + cc - 2;
            float v = 0.0f;
            if (gh >= 0 && gh < Hv && gw >= 0 && gw < Wv)
                v = imgb[(gh * Wv + gw) * Cv];
            strip[r * SST + cc] = __uint_as_float(to_tf32(v));
        }
    }
    __syncthreads();

    // ---- B fragments: bf[s=kh][u][j] ----
    uint32_t bf[5][2][2];
    #pragma unroll
    for (int s = 0; s < 5; s++)
        #pragma unroll
        for (int u = 0; u < 2; u++) {
            bf[s][u][0] = __float_as_uint(Wsm[8 * s + tg][8 * u + g]);
            bf[s][u][1] = __float_as_uint(Wsm[8 * s + tg + 4][8 * u + g]);
        }

    const int x = wrp * 16 + g;        // A-row m=g pixel (m=g+8 -> x+8)

    // 32-bit store addressing: element offset of (n=0, h=r0, w=px0+wrp*16+g)
    uint32_t obase = (uint32_t)(((b * Cv + c) * Hv + r0) * Wv + px0 + wrp * 16 + g);

    // ---- 5-row accumulator ring; walk 36 strip rows ----
    float acc[5][2][4] = {};

    #pragma unroll
    for (int ai = 0; ai < SRR; ai++) {
        const float* sr = strip + ai * SST + x;
        uint32_t a[4];
        a[0] = __float_as_uint(sr[tg]);
        a[1] = __float_as_uint(sr[8 + tg]);
        a[2] = t24 ? __float_as_uint(sr[4]) : 0u;
        a[3] = t24 ? __float_as_uint(sr[12]) : 0u;

        #pragma unroll
        for (int s = 0; s < 5; s++) {
            const int r = ai - s;
            if (r >= 0 && r < ROWS) {
                const int sl = r % 5;
                mma_tf32(acc[sl][0], a, bf[s][0][0], bf[s][0][1]);
                mma_tf32(acc[sl][1], a, bf[s][1][0], bf[s][1][1]);
            }
        }

        const int rd = ai - 4;          // completed output row
        if (rd >= 0) {
            const int sl = rd % 5;
            const uint32_t ob = obase + (uint32_t)rd * Wv;
            out[ob + (uint32_t)(2 * tg)     * NS]     = acc[sl][0][0];
            out[ob + (uint32_t)(2 * tg + 1) * NS]     = acc[sl][0][1];
            out[ob + (uint32_t)(2 * tg)     * NS + 8] = acc[sl][0][2];
            out[ob + (uint32_t)(2 * tg + 1) * NS + 8] = acc[sl][0][3];
            if (t24) {                   // n = 8, 9
                out[ob + 8u * NS]     = acc[sl][1][0];
                out[ob + 9u * NS]     = acc[sl][1][1];
                out[ob + 8u * NS + 8] = acc[sl][1][2];
                out[ob + 9u * NS + 8] = acc[sl][1][3];
            }
            #pragma unroll
            for (int u = 0; u < 2; u++)
                #pragma unroll
                for (int q = 0; q < 4; q++)
                    acc[sl][u][q] = 0.0f;
        }
    }
}

extern "C" void kernel_launch(void* const* d_in, const int* in_sizes, int n_in,
                              void* d_out, int out_size)
{
    const float* images  = (const float*)d_in[0];   // [B,H,W,C]
    const float* kernels = (const float*)d_in[1];   // [B,KH,KW,N]
    float* out = (float*)d_out;                     // [N,B,C,H,W]

    dim3 block(NT, 1, 1);
    dim3 grid((Wv / PXB) * (Hv / ROWS), Cv, Bv);   // (8, 3, 64)
    cdna_mma_kernel<<<grid, block>>>(images, kernels, out);
}

// round 13
// speedup vs baseline: 1.0703x; 1.0626x over previous
#include <cuda_runtime.h>
#include <cstdint>

// Problem dims (fixed)
#define Bv 64
#define Hv 128
#define Wv 128
#define Cv 3
#define Nv 10

#define ROWS 32                // output rows per CTA
#define SRR (ROWS + 4)         // 36 strip rows
#define PXB 64                 // pixels (width) per CTA
#define SST 76                 // strip row stride (76 % 32 = 12); full width staged finite
#define NT 128                 // 4 warps, one 16-px col tile each

__device__ __forceinline__ uint32_t to_tf32(float v) {
    uint32_t u;
    asm("cvt.rna.tf32.f32 %0, %1;" : "=r"(u) : "f"(v));
    return u;
}

__device__ __forceinline__ void mma_tf32(float c[4], const uint32_t a[4],
                                         uint32_t b0, uint32_t b1) {
    asm("mma.sync.aligned.m16n8k8.row.col.f32.tf32.tf32.f32 "
        "{%0,%1,%2,%3}, {%4,%5,%6,%7}, {%8,%9}, {%0,%1,%2,%3};"
        : "+f"(c[0]), "+f"(c[1]), "+f"(c[2]), "+f"(c[3])
        : "r"(a[0]), "r"(a[1]), "r"(a[2]), "r"(a[3]), "r"(b0), "r"(b1));
}

// out[n][b][c][h][w] = sum_{kh,kw} images[b][h+kh-2][w+kw-2][c] * kernels[b][kh][kw][n]
// GEMM per (b,c): M = n (16, pad from 10), N = 8 pixels, K = kw slots (kh-major,
// k = 8*kh + kw; kw 5..7 zero-WEIGHTED so image fragments need no masking).
// A = weights (register-resident), B = image fragment, C: thread holds adjacent
// pixel pairs -> STG.64 stores. One strip-row fragment pair serves all 5 kh groups.
__global__ __launch_bounds__(NT, 5)
void cdna_mma_kernel(const float* __restrict__ images,
                     const float* __restrict__ kernels,
                     float* __restrict__ out)
{
    __shared__ float strip[SRR * SST];   // tf32-rounded image strip (full stride, finite)
    __shared__ float Wsm[40][16];        // tf32-rounded weights [k=8kh+kw][n], zero pad

    const int tid  = threadIdx.x;
    const int lane = tid & 31;
    const int wrp  = tid >> 5;         // 0..3: 16-px column tile
    const int g    = lane >> 2;        // 0..7
    const int tg   = lane & 3;         // 0..3

    const int bx = blockIdx.x & 1;     // width half
    const int rt = blockIdx.x >> 1;    // row tile 0..3
    const int c  = blockIdx.y;
    const int b  = blockIdx.z;
    const int r0 = rt * ROWS;
    const int px0 = bx * PXB;

    // ---- stage W: [k=40][n=16], kh-major slots, tf32-rounded, pad -> 0 ----
    for (int i = tid; i < 640; i += NT) {
        int k = i >> 4, n = i & 15;
        int s = k >> 3, t = k & 7;
        float v = 0.0f;
        if (t < 5 && n < Nv) v = kernels[(b * 25 + s * 5 + t) * Nv + n];
        Wsm[k][n] = __uint_as_float(to_tf32(v));
    }

    // ---- stage strip: FULL 76-col stride so every reachable col is finite ----
    const float* imgb = images + ((size_t)b * Hv) * (Wv * Cv) + c;
    #pragma unroll
    for (int it = 0; it < (SRR * SST + NT - 1) / NT; it++) {
        int i = it * NT + tid;
        if (i < SRR * SST) {
            int r  = i / SST;
            int cc = i - r * SST;
            int gh = r0 + r - 2;
            int gw = px0 + cc - 2;
            float v = 0.0f;
            if (gh >= 0 && gh < Hv && gw >= 0 && gw < Wv)
                v = imgb[(gh * Wv + gw) * Cv];
            strip[r * SST + cc] = __uint_as_float(to_tf32(v));
        }
    }
    __syncthreads();

    // ---- A (weight) fragments, resident: wf[s] = {(g,tg),(g+8,tg),(g,tg+4),(g+8,tg+4)} ----
    uint32_t wf[5][4];
    #pragma unroll
    for (int s = 0; s < 5; s++) {
        wf[s][0] = __float_as_uint(Wsm[8 * s + tg][g]);
        wf[s][1] = __float_as_uint(Wsm[8 * s + tg][g + 8]);
        wf[s][2] = __float_as_uint(Wsm[8 * s + tg + 4][g]);
        wf[s][3] = __float_as_uint(Wsm[8 * s + tg + 4][g + 8]);
    }

    const size_t ns = (size_t)Bv * Cv * Hv * Wv;
    float* outbc = out + (((size_t)b * Cv + c) * Hv + r0) * Wv + px0;
    const float* sbase = strip + wrp * 16 + g;

    // ---- 5-row accumulator ring; walk 36 strip rows ----
    float acc[5][2][4] = {};

    #pragma unroll
    for (int ai = 0; ai < SRR; ai++) {
        const float* sr = sbase + ai * SST;
        // B fragments: tile0 (px wrp*16+0..7) and tile1 (+8); kw shift = +tg / +tg+4.
        // No masking: kw slots 5..7 have zero weights in A.
        const uint32_t f0 = __float_as_uint(sr[tg]);
        const uint32_t f1 = __float_as_uint(sr[tg + 4]);
        const uint32_t f2 = __float_as_uint(sr[8 + tg]);
        const uint32_t f3 = __float_as_uint(sr[8 + tg + 4]);

        #pragma unroll
        for (int s = 0; s < 5; s++) {
            const int r = ai - s;
            if (r >= 0 && r < ROWS) {
                const int sl = r % 5;
                mma_tf32(acc[sl][0], wf[s], f0, f1);   // tile0: px 0..7
                mma_tf32(acc[sl][1], wf[s], f2, f3);   // tile1: px 8..15
            }
        }

        const int rd = ai - 4;          // completed output row
        if (rd >= 0) {
            const int sl = rd % 5;
            // thread holds px pair (2tg, 2tg+1) for n=g and n=g+8 -> STG.64
            float* base = outbc + (size_t)rd * Wv + wrp * 16 + 2 * tg;
            float2 v00 = make_float2(acc[sl][0][0], acc[sl][0][1]);
            float2 v01 = make_float2(acc[sl][1][0], acc[sl][1][1]);
            *reinterpret_cast<float2*>(base + (size_t)g * ns)     = v00;
            *reinterpret_cast<float2*>(base + (size_t)g * ns + 8) = v01;
            if (g < 2) {                 // n = 8, 9
                float2 v10 = make_float2(acc[sl][0][2], acc[sl][0][3]);
                float2 v11 = make_float2(acc[sl][1][2], acc[sl][1][3]);
                *reinterpret_cast<float2*>(base + (size_t)(g + 8) * ns)     = v10;
                *reinterpret_cast<float2*>(base + (size_t)(g + 8) * ns + 8) = v11;
            }
            #pragma unroll
            for (int u = 0; u < 2; u++)
                #pragma unroll
                for (int q = 0; q < 4; q++)
                    acc[sl][u][q] = 0.0f;
        }
    }
}

extern "C" void kernel_launch(void* const* d_in, const int* in_sizes, int n_in,
                              void* d_out, int out_size)
{
    const float* images  = (const float*)d_in[0];   // [B,H,W,C]
    const float* kernels = (const float*)d_in[1];   // [B,KH,KW,N]
    float* out = (float*)d_out;                     // [N,B,C,H,W]

    dim3 block(NT, 1, 1);
    dim3 grid((Wv / PXB) * (Hv / ROWS), Cv, Bv);   // (8, 3, 64)
    cdna_mma_kernel<<<grid, block>>>(images, kernels, out);
}